// round 5
// baseline (speedup 1.0000x reference)
#include <cuda_runtime.h>

#define RES    128
#define FEAT   18
#define TPB    128
#define NWARP  (TPB / 32)
#define CBSIZE (RES * RES * RES * FEAT)   // 37748736 floats
#define WIN    40                          // floats per aligned region window
#define PPAD   11                          // float4 chunks/point in smem (176B: conflict-free)

// issue 11 gather loads for round R into registers (no smem yet)
template<int R>
__device__ __forceinline__ void ldg_round(const float* __restrict__ cb,
                                          const int o_r[4],
                                          int gc, int gpb, bool glv,
                                          float4 reg[11])
{
    #pragma unroll
    for (int j = 0; j < 11; j++) {
        const int p = gpb + 3 * j;                       // target point 0..32
        const int o = __shfl_sync(0xffffffffu, o_r[R], p & 31);
        if (glv && p < 32) {
            const int ba = min(o & ~3, CBSIZE - WIN);    // 16B-aligned, end-clamped
            reg[j] = __ldg((const float4*)cb + (ba >> 2) + gc);
        }
    }
}

__device__ __forceinline__ void sts_round(float4 (*bufb)[PPAD],
                                          int gc, int gpb, bool glv,
                                          const float4 reg[11])
{
    #pragma unroll
    for (int j = 0; j < 11; j++) {
        const int p = gpb + 3 * j;
        if (glv && p < 32)
            bufb[p][gc] = reg[j];
    }
}

// consume own point's staged window for round R
template<int R>
__device__ __forceinline__ void consume(const float4* bufl,   // buf[w][b][lane]
                                        const int o_r[4],
                                        float wx0, float wx1,
                                        float wy0, float wy1,
                                        float wz0, float wz1,
                                        float acc[FEAT])
{
    const int   o   = o_r[R];
    const int   ba  = min(o & ~3, CBSIZE - WIN);
    const int   par = o - ba;                 // 0, 2, or 4
    const bool  s0  = (par == 0);
    const bool  s1  = (par == 2);
    const float wyz = ((R & 1) ? wy1 : wy0) * ((R & 2) ? wz1 : wz0);
    const float wA  = wx0 * wyz;
    const float wB  = wx1 * wyz;

    float win[24];
    // corner A: needs window floats [par .. par+17], chunks 0..5
    #pragma unroll
    for (int k = 0; k < 6; k++) {
        const float4 q = bufl[k];
        win[4*k+0] = q.x; win[4*k+1] = q.y; win[4*k+2] = q.z; win[4*k+3] = q.w;
    }
    #pragma unroll
    for (int j = 0; j < FEAT; j++) {
        const float vA = s0 ? win[j] : (s1 ? win[j + 2] : win[j + 4]);
        acc[j] = fmaf(wA, vA, acc[j]);
    }
    // corner B: needs [par+18 .. par+35], chunks 4..9 (local base = float 16)
    #pragma unroll
    for (int k = 0; k < 6; k++) {
        const float4 q = bufl[k + 4];
        win[4*k+0] = q.x; win[4*k+1] = q.y; win[4*k+2] = q.z; win[4*k+3] = q.w;
    }
    #pragma unroll
    for (int j = 0; j < FEAT; j++) {
        const float vB = s0 ? win[j + 2] : (s1 ? win[j + 4] : win[j + 6]);
        acc[j] = fmaf(wB, vB, acc[j]);
    }
}

__global__ __launch_bounds__(TPB, 5)
void densegrid_pipe_kernel(const float* __restrict__ pts,
                           const float* __restrict__ cb,
                           const float* __restrict__ T,
                           float* __restrict__ out,
                           int N)
{
    __shared__ float4 buf[NWARP][2][32][PPAD];   // 45056 B, double-buffered staging

    const int tid  = threadIdx.x;
    const int w    = tid >> 5;
    const int lane = tid & 31;
    const int n    = blockIdx.x * TPB + tid;

    // ---- transform inverse (broadcast) ----
    const float a  = __ldg(T + 0), b  = __ldg(T + 1), c_ = __ldg(T + 2),  tx = __ldg(T + 3);
    const float d  = __ldg(T + 4), e  = __ldg(T + 5), f  = __ldg(T + 6),  ty = __ldg(T + 7);
    const float g  = __ldg(T + 8), h  = __ldg(T + 9), ii = __ldg(T + 10), tz = __ldg(T + 11);

    const float det = a * (e * ii - f * h) - b * (d * ii - f * g) + c_ * (d * h - e * g);
    const float rd  = 1.0f / det;
    const float m00 = (e * ii - f * h) * rd,  m01 = (c_ * h - b * ii) * rd,  m02 = (b * f - c_ * e) * rd;
    const float m10 = (f * g - d * ii) * rd,  m11 = (a * ii - c_ * g) * rd,  m12 = (c_ * d - a * f) * rd;
    const float m20 = (d * h - e * g) * rd,   m21 = (b * g - a * h) * rd,    m22 = (a * e - b * d) * rd;

    // ---- per-point setup ----
    float wx0 = 0.f, wx1 = 0.f, wy0 = 0.f, wy1 = 0.f, wz0 = 0.f, wz1 = 0.f;
    int o_r[4] = {0, 0, 0, 0};

    if (n < N) {
        const float qx = __ldcs(pts + 3 * n + 0) - tx;
        const float qy = __ldcs(pts + 3 * n + 1) - ty;
        const float qz = __ldcs(pts + 3 * n + 2) - tz;

        float px = (m00 * qx + m01 * qy + m02 * qz) * (float)(RES - 1);
        float py = (m10 * qx + m11 * qy + m12 * qz) * (float)(RES - 1);
        float pz = (m20 * qx + m21 * qy + m22 * qz) * (float)(RES - 1);

        const float fx = floorf(px), fy = floorf(py), fz = floorf(pz);
        wx1 = px - fx; wx0 = 1.0f - wx1;
        wy1 = py - fy; wy0 = 1.0f - wy1;
        wz1 = pz - fz; wz0 = 1.0f - wz1;

        int ix0 = max(0, min(RES - 1, (int)fx));
        int iy0 = max(0, min(RES - 1, (int)fy));
        int iz0 = max(0, min(RES - 1, (int)fz));
        const int iy1 = min(iy0 + 1, RES - 1);
        const int iz1 = min(iz0 + 1, RES - 1);
        // ix1 = ix0+1 (clamped window covers both x-corners contiguously)

        #pragma unroll
        for (int r = 0; r < 4; r++) {
            const int yy = (r & 1) ? iy1 : iy0;
            const int zz = (r & 2) ? iz1 : iz0;
            o_r[r] = (ix0 + yy * RES + zz * RES * RES) * FEAT;
        }
    }

    // gather lane mapping
    const int  gc  = lane % 10;     // chunk 0..9
    const int  gpb = lane / 10;     // point base 0..2 (lanes 30,31 idle for loads)
    const bool glv = (lane < 30);

    float acc[FEAT];
    #pragma unroll
    for (int j = 0; j < FEAT; j++) acc[j] = 0.0f;

    float4 reg[11];

    // ---- software pipeline: LDG0 STS0 LDG1 | CONS0 STS1 LDG2 | CONS1 STS2 LDG3 | CONS2 STS3 | CONS3
    ldg_round<0>(cb, o_r, gc, gpb, glv, reg);
    sts_round(buf[w][0], gc, gpb, glv, reg);
    ldg_round<1>(cb, o_r, gc, gpb, glv, reg);
    __syncwarp();

    consume<0>(buf[w][0][lane], o_r, wx0, wx1, wy0, wy1, wz0, wz1, acc);
    sts_round(buf[w][1], gc, gpb, glv, reg);
    ldg_round<2>(cb, o_r, gc, gpb, glv, reg);
    __syncwarp();

    consume<1>(buf[w][1][lane], o_r, wx0, wx1, wy0, wy1, wz0, wz1, acc);
    sts_round(buf[w][0], gc, gpb, glv, reg);
    ldg_round<3>(cb, o_r, gc, gpb, glv, reg);
    __syncwarp();

    consume<2>(buf[w][0][lane], o_r, wx0, wx1, wy0, wy1, wz0, wz1, acc);
    sts_round(buf[w][1], gc, gpb, glv, reg);
    __syncwarp();

    consume<3>(buf[w][1][lane], o_r, wx0, wx1, wy0, wy1, wz0, wz1, acc);

    // ---- output: stage in smem (reuse buf), then coalesced float4 streaming stores ----
    __syncthreads();
    float* stage = (float*)&buf[0][0][0][0];
    #pragma unroll
    for (int j = 0; j < FEAT; j++)
        stage[tid * FEAT + j] = acc[j];
    __syncthreads();

    const long long blockBase = (long long)blockIdx.x * TPB * FEAT;
    const long long remain    = (long long)N * FEAT - blockBase;

    if (remain >= (long long)TPB * FEAT) {
        const float4* s4 = (const float4*)stage;
        float4* o4 = (float4*)(out + blockBase);
        #pragma unroll
        for (int i = tid; i < TPB * FEAT / 4; i += TPB)
            __stcs(o4 + i, s4[i]);
    } else if (remain > 0) {
        float* op = out + blockBase;
        for (int i = tid; i < (int)remain; i += TPB)
            __stcs(op + i, stage[i]);
    }
}

extern "C" void kernel_launch(void* const* d_in, const int* in_sizes, int n_in,
                              void* d_out, int out_size)
{
    const float* pts = (const float*)d_in[0];
    const float* cb  = (const float*)d_in[1];
    const float* T   = (const float*)d_in[2];
    float* out       = (float*)d_out;

    const int N = in_sizes[0] / 3;
    const int blocks = (N + TPB - 1) / TPB;
    densegrid_pipe_kernel<<<blocks, TPB>>>(pts, cb, T, out, N);
}

// round 8
// speedup vs baseline: 1.0378x; 1.0378x over previous
#include <cuda_runtime.h>

#define RES    128
#define FEAT   18
#define TPB    128
#define NWARP  (TPB / 32)
#define CBSIZE (RES * RES * RES * FEAT)   // 37748736 floats
#define WIN    40                          // floats per aligned region window
#define PPAD   11                          // float4 chunks/point slot (176B, odd stride)

__device__ __forceinline__ void cp_async16(unsigned smem_addr, const void* gptr) {
    asm volatile("cp.async.ca.shared.global [%0], [%1], 16;\n"
                 :: "r"(smem_addr), "l"(gptr) : "memory");
}
__device__ __forceinline__ void cp_commit() {
    asm volatile("cp.async.commit_group;\n" ::: "memory");
}
template<int N_>
__device__ __forceinline__ void cp_wait() {
    asm volatile("cp.async.wait_group %0;\n" :: "n"(N_) : "memory");
}

// ---- issue one sub-round S (region r=S>>1, half h=S&1): 6 LDGSTS per warp ----
template<int S>
__device__ __forceinline__ void issue_sub(const float* __restrict__ cb,
                                          unsigned sbase,       // smem addr of stage[S%3][w]
                                          const int o_r[4],
                                          int lane)
{
    constexpr int R = S >> 1;
    constexpr int H = S & 1;
    const int gc  = lane % 10;          // chunk 0..9
    const int gpb = lane / 10;          // 0..3 (lanes 30,31 masked off)
    const bool glv = (lane < 30);

    #pragma unroll
    for (int j = 0; j < 6; j++) {
        const int pl = gpb + 3 * j;                     // point-in-half 0..17
        const int o  = __shfl_sync(0xffffffffu, o_r[R], (H * 16 + pl) & 31);
        if (glv && pl < 16) {
            const int ba = min(o & ~3, CBSIZE - WIN);   // 16B-aligned, end-clamped
            cp_async16(sbase + (unsigned)(pl * (PPAD * 16) + gc * 16),
                       (const char*)cb + (size_t)ba * 4u + (unsigned)(gc * 16));  // FIX: +gc chunk offset
        }
    }
    cp_commit();
}

// ---- consume sub-round S: lanes of half H accumulate region R ----
template<int S>
__device__ __forceinline__ void consume_sub(const float4* bufp,  // stage[S%3][w][lane&15]
                                            const int o_r[4],
                                            float wx0, float wx1,
                                            float wy0, float wy1,
                                            float wz0, float wz1,
                                            int lane,
                                            float acc[FEAT])
{
    constexpr int R = S >> 1;
    constexpr int H = S & 1;
    if ((lane >> 4) != H) return;

    const int   o   = o_r[R];
    const int   ba  = min(o & ~3, CBSIZE - WIN);
    const int   par = o - ba;                 // 0, 2, or 4
    const bool  s0  = (par == 0);
    const bool  s1  = (par == 2);
    const float wyz = ((R & 1) ? wy1 : wy0) * ((R & 2) ? wz1 : wz0);
    const float wA  = wx0 * wyz;
    const float wB  = wx1 * wyz;

    float win[24];
    // corner A: window floats [par .. par+17], chunks 0..5
    #pragma unroll
    for (int k = 0; k < 6; k++) {
        const float4 q = bufp[k];
        win[4*k+0] = q.x; win[4*k+1] = q.y; win[4*k+2] = q.z; win[4*k+3] = q.w;
    }
    #pragma unroll
    for (int j = 0; j < FEAT; j++) {
        const float vA = s0 ? win[j] : (s1 ? win[j + 2] : win[j + 4]);
        acc[j] = fmaf(wA, vA, acc[j]);
    }
    // corner B: window floats [par+18 .. par+35], chunks 4..9 (local base float 16)
    #pragma unroll
    for (int k = 0; k < 6; k++) {
        const float4 q = bufp[k + 4];
        win[4*k+0] = q.x; win[4*k+1] = q.y; win[4*k+2] = q.z; win[4*k+3] = q.w;
    }
    #pragma unroll
    for (int j = 0; j < FEAT; j++) {
        const float vB = s0 ? win[j + 2] : (s1 ? win[j + 4] : win[j + 6]);
        acc[j] = fmaf(wB, vB, acc[j]);
    }
}

__global__ __launch_bounds__(TPB, 6)
void densegrid_cpasync_kernel(const float* __restrict__ pts,
                              const float* __restrict__ cb,
                              const float* __restrict__ T,
                              float* __restrict__ out,
                              int N)
{
    // 3 rolling buffers x NWARP warps x 16 points x 11 float4 = 33792 B
    __shared__ float4 stage[3][NWARP][16][PPAD];

    const int tid  = threadIdx.x;
    const int w    = tid >> 5;
    const int lane = tid & 31;
    const int n    = blockIdx.x * TPB + tid;

    // ---- transform inverse (broadcast) ----
    const float a  = __ldg(T + 0), b  = __ldg(T + 1), c_ = __ldg(T + 2),  tx = __ldg(T + 3);
    const float d  = __ldg(T + 4), e  = __ldg(T + 5), f  = __ldg(T + 6),  ty = __ldg(T + 7);
    const float g  = __ldg(T + 8), h  = __ldg(T + 9), ii = __ldg(T + 10), tz = __ldg(T + 11);

    const float det = a * (e * ii - f * h) - b * (d * ii - f * g) + c_ * (d * h - e * g);
    const float rd  = 1.0f / det;
    const float m00 = (e * ii - f * h) * rd,  m01 = (c_ * h - b * ii) * rd,  m02 = (b * f - c_ * e) * rd;
    const float m10 = (f * g - d * ii) * rd,  m11 = (a * ii - c_ * g) * rd,  m12 = (c_ * d - a * f) * rd;
    const float m20 = (d * h - e * g) * rd,   m21 = (b * g - a * h) * rd,    m22 = (a * e - b * d) * rd;

    // ---- per-point setup ----
    float wx0 = 0.f, wx1 = 0.f, wy0 = 0.f, wy1 = 0.f, wz0 = 0.f, wz1 = 0.f;
    int o_r[4] = {0, 0, 0, 0};

    if (n < N) {
        const float qx = __ldcs(pts + 3 * n + 0) - tx;
        const float qy = __ldcs(pts + 3 * n + 1) - ty;
        const float qz = __ldcs(pts + 3 * n + 2) - tz;

        float px = (m00 * qx + m01 * qy + m02 * qz) * (float)(RES - 1);
        float py = (m10 * qx + m11 * qy + m12 * qz) * (float)(RES - 1);
        float pz = (m20 * qx + m21 * qy + m22 * qz) * (float)(RES - 1);

        const float fx = floorf(px), fy = floorf(py), fz = floorf(pz);
        wx1 = px - fx; wx0 = 1.0f - wx1;
        wy1 = py - fy; wy0 = 1.0f - wy1;
        wz1 = pz - fz; wz0 = 1.0f - wz1;

        int ix0 = max(0, min(RES - 1, (int)fx));
        int iy0 = max(0, min(RES - 1, (int)fy));
        int iz0 = max(0, min(RES - 1, (int)fz));
        const int iy1 = min(iy0 + 1, RES - 1);
        const int iz1 = min(iz0 + 1, RES - 1);
        // ix1 = ix0+1 (window covers both x-corners contiguously, end-clamped)

        #pragma unroll
        for (int r = 0; r < 4; r++) {
            const int yy = (r & 1) ? iy1 : iy0;
            const int zz = (r & 2) ? iz1 : iz0;
            o_r[r] = (ix0 + yy * RES + zz * RES * RES) * FEAT;
        }
    }

    float acc[FEAT];
    #pragma unroll
    for (int j = 0; j < FEAT; j++) acc[j] = 0.0f;

    const unsigned sb0 = (unsigned)__cvta_generic_to_shared(&stage[0][w][0][0]);
    const unsigned sb1 = (unsigned)__cvta_generic_to_shared(&stage[1][w][0][0]);
    const unsigned sb2 = (unsigned)__cvta_generic_to_shared(&stage[2][w][0][0]);
    const unsigned sb[3] = { sb0, sb1, sb2 };

    // ---- async pipeline: 3 sub-rounds in flight, 8 sub-rounds total ----
    issue_sub<0>(cb, sb[0], o_r, lane);
    issue_sub<1>(cb, sb[1], o_r, lane);
    issue_sub<2>(cb, sb[2], o_r, lane);

    cp_wait<2>(); __syncwarp();
    consume_sub<0>(stage[0][w][lane & 15], o_r, wx0, wx1, wy0, wy1, wz0, wz1, lane, acc);
    __syncwarp();
    issue_sub<3>(cb, sb[0], o_r, lane);

    cp_wait<2>(); __syncwarp();
    consume_sub<1>(stage[1][w][lane & 15], o_r, wx0, wx1, wy0, wy1, wz0, wz1, lane, acc);
    __syncwarp();
    issue_sub<4>(cb, sb[1], o_r, lane);

    cp_wait<2>(); __syncwarp();
    consume_sub<2>(stage[2][w][lane & 15], o_r, wx0, wx1, wy0, wy1, wz0, wz1, lane, acc);
    __syncwarp();
    issue_sub<5>(cb, sb[2], o_r, lane);

    cp_wait<2>(); __syncwarp();
    consume_sub<3>(stage[0][w][lane & 15], o_r, wx0, wx1, wy0, wy1, wz0, wz1, lane, acc);
    __syncwarp();
    issue_sub<6>(cb, sb[0], o_r, lane);

    cp_wait<2>(); __syncwarp();
    consume_sub<4>(stage[1][w][lane & 15], o_r, wx0, wx1, wy0, wy1, wz0, wz1, lane, acc);
    __syncwarp();
    issue_sub<7>(cb, sb[1], o_r, lane);

    cp_wait<2>(); __syncwarp();
    consume_sub<5>(stage[2][w][lane & 15], o_r, wx0, wx1, wy0, wy1, wz0, wz1, lane, acc);

    cp_wait<1>(); __syncwarp();
    consume_sub<6>(stage[0][w][lane & 15], o_r, wx0, wx1, wy0, wy1, wz0, wz1, lane, acc);

    cp_wait<0>(); __syncwarp();
    consume_sub<7>(stage[1][w][lane & 15], o_r, wx0, wx1, wy0, wy1, wz0, wz1, lane, acc);

    // ---- output: stage in smem (reuse stage buffers), coalesced float4 streaming ----
    __syncthreads();
    float* ostage = (float*)&stage[0][0][0][0];
    #pragma unroll
    for (int j = 0; j < FEAT; j++)
        ostage[tid * FEAT + j] = acc[j];
    __syncthreads();

    const long long blockBase = (long long)blockIdx.x * TPB * FEAT;
    const long long remain    = (long long)N * FEAT - blockBase;

    if (remain >= (long long)TPB * FEAT) {
        const float4* s4 = (const float4*)ostage;
        float4* o4 = (float4*)(out + blockBase);
        #pragma unroll
        for (int i = tid; i < TPB * FEAT / 4; i += TPB)
            __stcs(o4 + i, s4[i]);
    } else if (remain > 0) {
        float* op = out + blockBase;
        for (int i = tid; i < (int)remain; i += TPB)
            __stcs(op + i, ostage[i]);
    }
}

extern "C" void kernel_launch(void* const* d_in, const int* in_sizes, int n_in,
                              void* d_out, int out_size)
{
    const float* pts = (const float*)d_in[0];
    const float* cb  = (const float*)d_in[1];
    const float* T   = (const float*)d_in[2];
    float* out       = (float*)d_out;

    const int N = in_sizes[0] / 3;
    const int blocks = (N + TPB - 1) / TPB;
    densegrid_cpasync_kernel<<<blocks, TPB>>>(pts, cb, T, out, N);
}